// round 17
// baseline (speedup 1.0000x reference)
#include <cuda_runtime.h>
#include <cuda_fp16.h>

// Sub_MGU: block-diagonal MGU recurrence. B=64, T=2048, S=32, H=16.
//   f = sigmoid(x*Wif + b_if + Whf·h + b_hf)
//   n = tanh(x*Win + b_in + f*(Whn·h + b_hn))
//   h' = f*n + (1-f)*h
//
// R16 = R15 (HMMA + 16 time chunks, 90.1us) + STORE COALESCING:
// ncu showed L1 at 73.5% = the wall, and 16 store wavefronts per 8-chain
// step (4 scattered STG.32 x 4 lines) vs an intrinsic floor of 8.
// Fix: permute the MMA index space by pi(r) = 2*(r&7) + (r>>3), loading
// A[r][k] = W[pi(r)][pi(k)]. The movmatrix C->B handoff makes B's k-space
// equal C's row-space, so the permutation is self-consistent and exact.
// Lane then holds j = 2gid, 2gid+1 (per chain pair); two shfl.xor(4)
// exchanges give each lane 4 CONSECUTIVE j of ONE chain -> one STG.128
// = 8 wavefronts/step (halved), 1 instruction (was 4).
// Everything else identical to R15: 1 warp = 1 subunit x 8 chains,
// 2x mma.sync.m16n8k16 per step (tensor pipe), h fp32 in C layout,
// linearized gates (MUFU tanh anchors one step ahead), 16 chunks WARM=32.

#define SUB    32
#define HID    16
#define TSTEP  2048
#define SH     (SUB * HID)
#define WARM   32
#define STORED 128

typedef unsigned long long u64;
typedef unsigned int u32;

__device__ __forceinline__ u64 pack2(float lo, float hi) {
    u64 r; asm("mov.b64 %0, {%1, %2};" : "=l"(r) : "f"(lo), "f"(hi)); return r;
}
__device__ __forceinline__ void unpack2(u64 v, float& lo, float& hi) {
    asm("mov.b64 {%0, %1}, %2;" : "=f"(lo), "=f"(hi) : "l"(v));
}
__device__ __forceinline__ u64 fma2v(u64 a, u64 b, u64 c) {
    u64 d; asm("fma.rn.f32x2 %0, %1, %2, %3;" : "=l"(d) : "l"(a), "l"(b), "l"(c)); return d;
}
__device__ __forceinline__ u64 mul2(u64 a, u64 b) {
    u64 d; asm("mul.rn.f32x2 %0, %1, %2;" : "=l"(d) : "l"(a), "l"(b)); return d;
}
__device__ __forceinline__ float tanh_mufu(float v) {
    float r; asm("tanh.approx.f32 %0, %1;" : "=f"(r) : "f"(v)); return r;
}
__device__ __forceinline__ u64 tanh2(u64 v) {
    float a, b; unpack2(v, a, b);
    return pack2(tanh_mufu(a), tanh_mufu(b));
}
// d = f16x2 {lo, hi}  (PTX cvt packs first float operand into HIGH half)
__device__ __forceinline__ u32 cvtf16x2(float hi, float lo) {
    u32 d; asm("cvt.rn.f16x2.f32 %0, %1, %2;" : "=r"(d) : "f"(hi), "f"(lo)); return d;
}
__device__ __forceinline__ u32 movm_t(u32 v) {
    u32 d; asm("movmatrix.sync.aligned.m8n8.trans.b16 %0, %1;" : "=r"(d) : "r"(v)); return d;
}
#define MMA16816(D0,D1,D2,D3, A, B0,B1, C0,C1,C2,C3)                         \
    asm("mma.sync.aligned.m16n8k16.row.col.f32.f16.f16.f32 "                 \
        "{%0,%1,%2,%3},{%4,%5,%6,%7},{%8,%9},{%10,%11,%12,%13};"             \
        : "=f"(D0), "=f"(D1), "=f"(D2), "=f"(D3)                             \
        : "r"((A)[0]), "r"((A)[1]), "r"((A)[2]), "r"((A)[3]),                \
          "r"(B0), "r"(B1),                                                  \
          "f"(C0), "f"(C1), "f"(C2), "f"(C3))

__global__ __launch_bounds__(128, 7)
void mgu_kernel(const float* __restrict__ x,
                const float* __restrict__ Wif,
                const float* __restrict__ Win,
                const float* __restrict__ Whf,
                const float* __restrict__ Whn,
                const float* __restrict__ bhi,
                const float* __restrict__ bhh,
                float* __restrict__ out)
{
    const int tid  = threadIdx.x;
    const int lane = tid & 31;
    const int gid  = lane >> 2;      // 0..7  (fragment group id)
    const int tig  = lane & 3;       // 0..3  (thread in group)
    const int wl   = tid >> 5;       // warp in block
    const int w    = blockIdx.x * 4 + wl;   // 0..4095
    const int s    = w & (SUB - 1);  // subunit
    const int r    = w >> 5;         // 0..127
    const int bq   = r & 7;          // batch octet
    const int c    = r >> 3;         // time chunk 0..15
    const int b0   = bq * 8;

    const int t_start = c ? (STORED * c - WARM) : 0;
    const int nsteps  = c ? (STORED + WARM) : STORED;  // 160 or 128
    const int nwarm   = c ? WARM : 0;
    const int gclamp  = TSTEP - 16 - t_start;          // local prefetch clamp

    // permuted index space: C row r <-> true j = pi(r) = 2*(r&7) + (r>>3)
    const int jL = 2 * gid;          // true j of C rows 0..7 at row gid
    const int jH = 2 * gid + 1;      // true j of C rows 8..15 at row gid+8

    // per-warp x staging: [buf][step 0..15][chain 0..7]
    __shared__ float xs[4][2][16][8];
    float* xsw = &xs[wl][0][0][0];

    // ---- A fragments: A[r][k] = W[pi(r)][pi(k)], f16 (f-gate halved) ----
    //  pi(2tig)=4tig, pi(2tig+1)=4tig+2, pi(2tig+8)=4tig+1, pi(2tig+9)=4tig+3
    u32 Af[4], An[4];
    {
        const int baseL = (s * HID + jL) * HID;
        const int baseH = (s * HID + jH) * HID;
        Af[0] = cvtf16x2(0.5f * Whf[baseL + 4*tig + 2], 0.5f * Whf[baseL + 4*tig]);
        Af[1] = cvtf16x2(0.5f * Whf[baseH + 4*tig + 2], 0.5f * Whf[baseH + 4*tig]);
        Af[2] = cvtf16x2(0.5f * Whf[baseL + 4*tig + 3], 0.5f * Whf[baseL + 4*tig + 1]);
        Af[3] = cvtf16x2(0.5f * Whf[baseH + 4*tig + 3], 0.5f * Whf[baseH + 4*tig + 1]);
        An[0] = cvtf16x2(Whn[baseL + 4*tig + 2], Whn[baseL + 4*tig]);
        An[1] = cvtf16x2(Whn[baseH + 4*tig + 2], Whn[baseH + 4*tig]);
        An[2] = cvtf16x2(Whn[baseL + 4*tig + 3], Whn[baseL + 4*tig + 1]);
        An[3] = cvtf16x2(Whn[baseH + 4*tig + 3], Whn[baseH + 4*tig + 1]);
    }

    // ---- x-part constants (per lane: true j = jL and jH), packed x2 ----
    const float wifL = 0.5f * Wif[s * HID + jL];
    const float wifH = 0.5f * Wif[s * HID + jH];
    const float winL = Win[s * HID + jL];
    const float winH = Win[s * HID + jH];
    const float bf0L = 0.5f * (bhi[s * HID + jL] + bhh[s * HID + jL]);
    const float bf0H = 0.5f * (bhi[s * HID + jH] + bhh[s * HID + jH]);
    const float binL = bhi[SH + s * HID + jL];
    const float binH = bhi[SH + s * HID + jH];
    const float bhnL = bhh[SH + s * HID + jL];
    const float bhnH = bhh[SH + s * HID + jH];
    const u64 wif2L = pack2(wifL, wifL), wif2H = pack2(wifH, wifH);
    const u64 win2L = pack2(winL, winL), win2H = pack2(winH, winH);
    const u64 bf02L = pack2(bf0L, bf0L), bf02H = pack2(bf0H, bf0H);
    const u64 bin2L = pack2(binL, binL), bin2H = pack2(binH, binH);
    const u64 one2  = pack2(1.0f, 1.0f);
    const u64 half2 = pack2(0.5f, 0.5f);
    const u64 negone2 = pack2(-1.0f, -1.0f);

    // ---- x global pointers (offset by t_start) ----
    const int il = lane & 15;
    const int ch = lane >> 4;
    const float* xp[4];
#pragma unroll
    for (int q = 0; q < 4; q++)
        xp[q] = x + ((size_t)(b0 + q * 2 + ch) * TSTEP + t_start + il) * SUB + s;

    // ---- coalesced output: lane owns chain chn, j = jb..jb+3 (float4) ----
    const int chn = 2 * tig + (gid & 1);
    const int jb  = 2 * (gid & ~1);
    float4* o4 = reinterpret_cast<float4*>(
        out + ((size_t)(b0 + chn) * TSTEP + t_start) * SH + s * HID + jb);

    // ---- prologue: stage block 0 into buf 0; hold block 1 in regs ----
    float held[4];
#pragma unroll
    for (int q = 0; q < 4; q++) held[q] = xp[q][0];
#pragma unroll
    for (int q = 0; q < 4; q++) xsw[0 * 128 + il * 8 + (q * 2 + ch)] = held[q];
    __syncwarp();
#pragma unroll
    for (int q = 0; q < 4; q++) held[q] = xp[q][(size_t)16 * SUB];

    // ---- x-only gate params for the CURRENT step (linearization anchors)
    u64 Ff01, Ff23, uf01, uf23, ntf01, ntf23, tn01, tn23, ntn01, ntn23, un01, un23;
#define PRE(BUF, I) do {                                                      \
        const float2 xv = *reinterpret_cast<const float2*>(                   \
            &xsw[(BUF) * 128 + (I) * 8 + 2 * tig]);                           \
        const u64 x2 = pack2(xv.x, xv.y);                                     \
        const u64 af01 = fma2v(x2, wif2L, bf02L);                             \
        const u64 af23 = fma2v(x2, wif2H, bf02H);                             \
        const u64 an01 = fma2v(x2, win2L, bin2L);                             \
        const u64 an23 = fma2v(x2, win2H, bin2H);                             \
        const u64 tf01 = tanh2(af01);                                         \
        const u64 tf23 = tanh2(af23);                                         \
        tn01 = tanh2(an01);                                                   \
        tn23 = tanh2(an23);                                                   \
        Ff01 = fma2v(tf01, half2, half2);                                     \
        Ff23 = fma2v(tf23, half2, half2);                                     \
        ntf01 = mul2(tf01, negone2);                                          \
        ntf23 = mul2(tf23, negone2);                                          \
        uf01 = fma2v(mul2(ntf01, half2), tf01, half2);                        \
        uf23 = fma2v(mul2(ntf23, half2), tf23, half2);                        \
        ntn01 = mul2(tn01, negone2);                                          \
        ntn23 = mul2(tn23, negone2);                                          \
        un01 = fma2v(ntn01, tn01, one2);                                      \
        un23 = fma2v(ntn23, tn23, one2);                                      \
    } while (0)

    PRE(0, 0);

    u32 rb0 = 0u, rb1 = 0u;          // B fragment of h (f16) — h(start)=0
    u64 h01 = 0ull, h23 = 0ull;      // h state, fp32, C layout pairs

    for (int t0 = 0; t0 < nsteps; t0 += 16) {
        const int buf = (t0 >> 4) & 1;
        const bool store = (t0 >= nwarm);   // whole 16-blocks (nwarm = 0 or 32)
        // stage next block into buf^1; prefetch block t0+32 (clamped)
#pragma unroll
        for (int q = 0; q < 4; q++)
            xsw[(buf ^ 1) * 128 + il * 8 + (q * 2 + ch)] = held[q];
        __syncwarp();
        int tg = t0 + 32;
        if (tg > gclamp) tg = gclamp;
#pragma unroll
        for (int q = 0; q < 4; q++) held[q] = xp[q][(size_t)tg * SUB];

#pragma unroll
        for (int i = 0; i < 16; i++) {
            // ---- both gate GEMMs for all 8 chains (tensor pipe) ----
            float df0, df1, df2, df3, dn0, dn1, dn2, dn3;
            MMA16816(df0, df1, df2, df3, Af, rb0, rb1, 0.0f, 0.0f, 0.0f, 0.0f);
            MMA16816(dn0, dn1, dn2, dn3, An, rb0, rb1, bhnL, bhnL, bhnH, bhnH);

            // ---- gate tail, packed over chain pairs (lo=2tig, hi=2tig+1)
            const u64 d01 = pack2(df0, df1), dN01 = pack2(dn0, dn1);
            const u64 d23 = pack2(df2, df3), dN23 = pack2(dn2, dn3);

            const u64 f01 = fma2v(mul2(d01, uf01), fma2v(d01, ntf01, one2), Ff01);
            const u64 f23 = fma2v(mul2(d23, uf23), fma2v(d23, ntf23, one2), Ff23);

            const u64 e01 = mul2(f01, dN01);
            const u64 e23 = mul2(f23, dN23);
            const u64 n01 = fma2v(mul2(e01, un01), fma2v(e01, ntn01, one2), tn01);
            const u64 n23 = fma2v(mul2(e23, un23), fma2v(e23, ntn23, one2), tn23);

            const u64 dd01 = fma2v(h01, negone2, n01);   // n - h
            const u64 dd23 = fma2v(h23, negone2, n23);
            h01 = fma2v(f01, dd01, h01);                 // h' = h + f(n-h)
            h23 = fma2v(f23, dd23, h23);

            // ---- handoff: fp32 C-layout -> f16 B fragment (transpose) ----
            float h0l, h0h, h2l, h2h;
            unpack2(h01, h0l, h0h);
            unpack2(h23, h2l, h2h);
            rb0 = movm_t(cvtf16x2(h0h, h0l));
            rb1 = movm_t(cvtf16x2(h2h, h2l));

            // ---- coalesced output: 2 shfl.xor(4) + one STG.128 ----
            // h0l=(j=2g,cA) h0h=(2g,cB) h2l=(2g+1,cA) h2h=(2g+1,cB)
            if (store) {
                const bool odd = (gid & 1);
                const float s1 = __shfl_xor_sync(0xffffffffu, odd ? h0l : h0h, 4);
                const float s2 = __shfl_xor_sync(0xffffffffu, odd ? h2l : h2h, 4);
                float4 v;
                if (odd) v = make_float4(s1, s2, h0h, h2h);   // j = 2(g-1)..2g+1
                else     v = make_float4(h0l, h2l, s1, s2);   // j = 2g..2g+3
                o4[(size_t)(t0 + i) * (SH / 4)] = v;
            }

            // ---- precompute next step's x-only gate params (off-path) ----
            if (i < 15) { PRE(buf, i + 1); }
            else        { PRE(buf ^ 1, 0); }
        }
    }
#undef PRE
}

extern "C" void kernel_launch(void* const* d_in, const int* in_sizes, int n_in,
                              void* d_out, int out_size)
{
    const float* x   = (const float*)d_in[0];
    const float* Wif = (const float*)d_in[1];
    const float* Win = (const float*)d_in[2];
    const float* Whf = (const float*)d_in[3];
    const float* Whn = (const float*)d_in[4];
    const float* bhi = (const float*)d_in[5];
    const float* bhh = (const float*)d_in[6];

    // 4096 warps = 32 subunits * 8 batch-octets * 16 time chunks;
    // 4 warps/block -> 1024 blocks; launch_bounds(128,7) -> one full wave.
    mgu_kernel<<<1024, 128>>>(x, Wif, Win, Whf, Whn, bhi, bhh, (float*)d_out);
}